// round 3
// baseline (speedup 1.0000x reference)
#include <cuda_runtime.h>

#define NN 100000
#define NE 1600000
#define DIM 32
#define NT 50000
#define NR 64

#define SCAN_B 512
#define SCAN_NB ((NN + SCAN_B - 1) / SCAN_B)  // 196

// ---------------- scratch (static device globals; no allocation) ----------------
// All referenced ONLY from device code (never passed from host).
__device__ int g_deg[NN];
__device__ int g_rowptr[NN + 1];
__device__ int g_cursor[NN];
__device__ int g_bsums[SCAN_NB];
__device__ int g_boff[SCAN_NB];
__device__ __align__(8) int2 g_edge[NE];           // (src, dis[src] bits) per CSR slot
__device__ float g_dis[NN];
__device__ __align__(16) float g_a[NN * DIM];      // x @ W1^T
__device__ __align__(16) float g_b[NN * DIM];      // relu-aggregate(layer1) @ W2^T
__device__ __align__(16) float g_h[NN * DIM];      // final node embedding h2

// ---------------- degree / CSR build ----------------
__global__ void k_zero_deg() {
    int i = blockIdx.x * blockDim.x + threadIdx.x;
    if (i < NN) g_deg[i] = 0;
}

__global__ void k_count(const int* __restrict__ dst) {
    int i = blockIdx.x * blockDim.x + threadIdx.x;
    if (i < NE) atomicAdd(&g_deg[dst[i]], 1);
}

__global__ void k_dis() {
    int i = blockIdx.x * blockDim.x + threadIdx.x;
    if (i < NN) g_dis[i] = rsqrtf((float)(g_deg[i] + 1));   // +1 self-loop
}

__global__ void k_scanA() {
    __shared__ int s[SCAN_B];
    int t = threadIdx.x;
    int idx = blockIdx.x * SCAN_B + t;
    int v = (idx < NN) ? g_deg[idx] : 0;
    s[t] = v;
    __syncthreads();
    #pragma unroll
    for (int off = 1; off < SCAN_B; off <<= 1) {
        int tv = (t >= off) ? s[t - off] : 0;
        __syncthreads();
        s[t] += tv;
        __syncthreads();
    }
    if (idx < NN) g_rowptr[idx] = s[t] - v;   // block-local exclusive
    if (t == SCAN_B - 1) g_bsums[blockIdx.x] = s[t];
}

__global__ void k_scanB() {
    __shared__ int s[256];
    int t = threadIdx.x;
    int v = (t < SCAN_NB) ? g_bsums[t] : 0;
    s[t] = v;
    __syncthreads();
    for (int off = 1; off < 256; off <<= 1) {
        int tv = (t >= off) ? s[t - off] : 0;
        __syncthreads();
        s[t] += tv;
        __syncthreads();
    }
    if (t < SCAN_NB) g_boff[t] = s[t] - v;    // exclusive block offsets
}

__global__ void k_scanC() {
    int t = threadIdx.x;
    int idx = blockIdx.x * SCAN_B + t;
    if (idx < NN) {
        int r = g_rowptr[idx] + g_boff[blockIdx.x];
        g_rowptr[idx] = r;
        g_cursor[idx] = r;
    }
    if (idx == 0) g_rowptr[NN] = NE;
}

__global__ void k_fill(const int* __restrict__ src, const int* __restrict__ dst) {
    int i = blockIdx.x * blockDim.x + threadIdx.x;
    if (i >= NE) return;
    int d = dst[i];
    int s = src[i];
    int pos = atomicAdd(&g_cursor[d], 1);
    g_edge[pos] = make_int2(s, __float_as_int(g_dis[s]));
}

// ---------------- dense: g_a[n][j] = sum_k x[n][k] * W1[j][k] ----------------
__global__ void __launch_bounds__(256) k_mm(const float* __restrict__ in,
                                            const float* __restrict__ W) {
    __shared__ float sW[DIM * DIM];
    for (int i = threadIdx.x; i < DIM * DIM; i += blockDim.x) sW[i] = W[i];
    __syncthreads();
    int row = blockIdx.x * blockDim.x + threadIdx.x;
    if (row >= NN) return;
    float xv[DIM];
    const float4* xin = reinterpret_cast<const float4*>(in + row * DIM);
    #pragma unroll
    for (int q = 0; q < 8; q++) {
        float4 v = xin[q];
        xv[q * 4 + 0] = v.x; xv[q * 4 + 1] = v.y;
        xv[q * 4 + 2] = v.z; xv[q * 4 + 3] = v.w;
    }
    float4* o = reinterpret_cast<float4*>(g_a + row * DIM);
    #pragma unroll
    for (int jq = 0; jq < 8; jq++) {
        float4 r;
        #pragma unroll
        for (int jj = 0; jj < 4; jj++) {
            int j = jq * 4 + jj;
            float acc = 0.f;
            #pragma unroll
            for (int k = 0; k < DIM; k++) acc = fmaf(xv[k], sW[j * DIM + k], acc);
            (&r.x)[jj] = acc;
        }
        o[jq] = r;
    }
}

// ---------------- GCN gather: warp per destination node ----------------
// v = relu( dis[d] * sum_{s in nbr(d)} dis[s]*xw[s] + dis[d]^2 * xw[d] + bias )
// PHASE 0: in=g_a, out=g_b, fused with layer-2 linear (W2).
// PHASE 1: in=g_b, out=g_h, plain.
template <int PHASE>
__global__ void __launch_bounds__(256) k_gather(const float* __restrict__ bias,
                                                const float* __restrict__ W2) {
    const float* __restrict__ xw = (PHASE == 0) ? g_a : g_b;
    float* __restrict__ out      = (PHASE == 0) ? g_b : g_h;
    __shared__ float sW[DIM * 33];
    if (PHASE == 0) {
        for (int i = threadIdx.x; i < DIM * DIM; i += blockDim.x)
            sW[(i >> 5) * 33 + (i & 31)] = W2[i];
        __syncthreads();
    }
    int w = (blockIdx.x * blockDim.x + threadIdx.x) >> 5;
    int lane = threadIdx.x & 31;
    if (w >= NN) return;
    int d = w;
    int start = g_rowptr[d];
    int end = g_rowptr[d + 1];
    float acc = 0.f;
    for (int base = start; base < end; base += 32) {
        int idx = base + lane;
        bool ok = idx < end;
        int2 e = ok ? g_edge[idx] : make_int2(0, 0);
        int m = min(32, end - base);
        for (int k = 0; k < m; k++) {
            int s = __shfl_sync(0xffffffffu, e.x, k);
            float ds = __int_as_float(__shfl_sync(0xffffffffu, e.y, k));
            acc = fmaf(xw[s * DIM + lane], ds, acc);   // coalesced 128B gather
        }
    }
    float dd = g_dis[d];
    float xwd = xw[d * DIM + lane];
    float v = fmaxf(fmaf(dd, acc, fmaf(dd * dd, xwd, bias[lane])), 0.f);
    if (PHASE == 1) {
        out[d * DIM + lane] = v;
    } else {
        float o = 0.f;
        #pragma unroll
        for (int k = 0; k < DIM; k++)
            o = fmaf(__shfl_sync(0xffffffffu, v, k), sW[lane * 33 + k], o);
        out[d * DIM + lane] = o;
    }
}

// ---------------- triple embedding + dueling MLP heads ----------------
__device__ __forceinline__ float lay(float x, const float* sw, const float* sb, int lane) {
    float acc = sb[lane];
    #pragma unroll
    for (int k = 0; k < DIM; k++)
        acc = fmaf(__shfl_sync(0xffffffffu, x, k), sw[lane * 33 + k], acc);
    return fmaxf(acc, 0.f);
}

__global__ void __launch_bounds__(256) k_triple(
    const int* __restrict__ head, const int* __restrict__ tail, const int* __restrict__ rel,
    const float* __restrict__ rel_emb,
    const float* __restrict__ aw1, const float* __restrict__ ab1,
    const float* __restrict__ aw2, const float* __restrict__ ab2,
    const float* __restrict__ aw3, const float* __restrict__ ab3,
    const float* __restrict__ vw1, const float* __restrict__ vb1,
    const float* __restrict__ vw2, const float* __restrict__ vb2,
    const float* __restrict__ vw3, const float* __restrict__ vb3,
    float* __restrict__ out) {
    __shared__ float s_aw1[DIM * 33], s_aw2[DIM * 33], s_vw1[DIM * 33], s_vw2[DIM * 33];
    __shared__ float s_aw3[3 * 33], s_vw3[DIM];
    __shared__ float s_ab1[DIM], s_ab2[DIM], s_ab3[3], s_vb1[DIM], s_vb2[DIM];
    __shared__ float s_vb3;
    __shared__ float s_rel[NR * DIM];
    int tid = threadIdx.x;
    for (int i = tid; i < DIM * DIM; i += blockDim.x) {
        int r = i >> 5, c = i & 31;
        s_aw1[r * 33 + c] = aw1[i];
        s_aw2[r * 33 + c] = aw2[i];
        s_vw1[r * 33 + c] = vw1[i];
        s_vw2[r * 33 + c] = vw2[i];
    }
    for (int i = tid; i < 3 * DIM; i += blockDim.x) s_aw3[(i >> 5) * 33 + (i & 31)] = aw3[i];
    for (int i = tid; i < NR * DIM; i += blockDim.x) s_rel[i] = rel_emb[i];
    if (tid < DIM) {
        s_vw3[tid] = vw3[tid];
        s_ab1[tid] = ab1[tid]; s_ab2[tid] = ab2[tid];
        s_vb1[tid] = vb1[tid]; s_vb2[tid] = vb2[tid];
    }
    if (tid < 3) s_ab3[tid] = ab3[tid];
    if (tid == 0) s_vb3 = vb3[0];
    __syncthreads();

    int w = (blockIdx.x * blockDim.x + tid) >> 5;
    int lane = tid & 31;
    if (w >= NT) return;
    int hd = head[w], tl = tail[w], r = rel[w];
    float xv = g_h[hd * DIM + lane] + s_rel[r * DIM + lane] + g_h[tl * DIM + lane];

    float a = lay(xv, s_aw1, s_ab1, lane);
    a = lay(a, s_aw2, s_ab2, lane);
    float v = lay(xv, s_vw1, s_vb1, lane);
    v = lay(v, s_vw2, s_vb2, lane);

    float a3 = (lane < 3) ? s_ab3[lane] : 0.f;
    float vacc = 0.f;
    #pragma unroll
    for (int k = 0; k < DIM; k++) {
        float ha = __shfl_sync(0xffffffffu, a, k);
        float hv = __shfl_sync(0xffffffffu, v, k);
        if (lane < 3) a3 = fmaf(ha, s_aw3[lane * 33 + k], a3);
        vacc = fmaf(hv, s_vw3[k], vacc);    // uniform across lanes
    }
    float val = s_vb3 + vacc;
    float a0 = __shfl_sync(0xffffffffu, a3, 0);
    float a1 = __shfl_sync(0xffffffffu, a3, 1);
    float a2 = __shfl_sync(0xffffffffu, a3, 2);
    float mean = (a0 + a1 + a2) * (1.f / 3.f);
    if (lane < 3) out[w * 3 + lane] = val + a3 - mean;
}

// ---------------- launch: pure kernel launches, only real device pointers ----------------
extern "C" void kernel_launch(void* const* d_in, const int* in_sizes, int n_in,
                              void* d_out, int out_size) {
    (void)in_sizes; (void)n_in; (void)out_size;
    const float* x       = (const float*)d_in[0];
    const int*   ei      = (const int*)d_in[1];
    const int*   head    = (const int*)d_in[2];
    const int*   tail    = (const int*)d_in[3];
    const int*   rel     = (const int*)d_in[4];
    const float* rel_emb = (const float*)d_in[5];
    const float* gw1 = (const float*)d_in[6];
    const float* gb1 = (const float*)d_in[7];
    const float* gw2 = (const float*)d_in[8];
    const float* gb2 = (const float*)d_in[9];
    const float* aw1 = (const float*)d_in[10];
    const float* ab1 = (const float*)d_in[11];
    const float* aw2 = (const float*)d_in[12];
    const float* ab2 = (const float*)d_in[13];
    const float* aw3 = (const float*)d_in[14];
    const float* ab3 = (const float*)d_in[15];
    const float* vw1 = (const float*)d_in[16];
    const float* vb1 = (const float*)d_in[17];
    const float* vw2 = (const float*)d_in[18];
    const float* vb2 = (const float*)d_in[19];
    const float* vw3 = (const float*)d_in[20];
    const float* vb3 = (const float*)d_in[21];
    float* out = (float*)d_out;

    const int* src = ei;
    const int* dst = ei + NE;

    // CSR build (shared by both GCN layers)
    k_zero_deg<<<(NN + 255) / 256, 256>>>();
    k_count<<<(NE + 255) / 256, 256>>>(dst);
    k_dis<<<(NN + 255) / 256, 256>>>();
    k_scanA<<<SCAN_NB, SCAN_B>>>();
    k_scanB<<<1, 256>>>();
    k_scanC<<<SCAN_NB, SCAN_B>>>();
    k_fill<<<(NE + 255) / 256, 256>>>(src, dst);

    // layer 1 linear: g_a = x @ W1^T
    k_mm<<<(NN + 255) / 256, 256>>>(x, gw1);
    // layer 1 aggregate + relu, fused with layer 2 linear: g_a -> g_b
    k_gather<0><<<(NN * 32 + 255) / 256, 256>>>(gb1, gw2);
    // layer 2 aggregate + relu: g_b -> g_h
    k_gather<1><<<(NN * 32 + 255) / 256, 256>>>(gb2, nullptr);

    // triples + dueling heads
    k_triple<<<(NT * 32 + 255) / 256, 256>>>(head, tail, rel, rel_emb,
                                             aw1, ab1, aw2, ab2, aw3, ab3,
                                             vw1, vb1, vw2, vb2, vw3, vb3, out);
}

// round 4
// speedup vs baseline: 1.0049x; 1.0049x over previous
#include <cuda_runtime.h>

#define NN 100000
#define NE 1600000
#define DIM 32
#define NT 50000
#define NR 64

#define SCAN_B 512
#define SCAN_NB ((NN + SCAN_B - 1) / SCAN_B)  // 196

// ---------------- scratch (static device globals; device-code access only) ----------------
__device__ int g_deg[NN];
__device__ int g_rowptr[NN + 1];
__device__ int g_cursor[NN];
__device__ unsigned long long g_scan_desc[SCAN_NB];  // (sum<<32)|flag; 1=agg, 2=prefix
__device__ __align__(8) int2 g_edge[NE];             // (src, dis[src] bits) per CSR slot
__device__ float g_dis[NN];
__device__ __align__(16) float g_a[NN * DIM];        // x @ W1^T
__device__ __align__(16) float g_b[NN * DIM];        // relu-aggregate(L1) @ W2^T
__device__ __align__(16) float g_h[NN * DIM];        // final node embedding

// ---------------- launch 0: layer-1 linear + zero deg + zero scan flags ----------------
__global__ void __launch_bounds__(256) k_mm_init(const float* __restrict__ in,
                                                 const float* __restrict__ W) {
    __shared__ float sW[DIM * DIM];
    for (int i = threadIdx.x; i < DIM * DIM; i += blockDim.x) sW[i] = W[i];
    __syncthreads();
    int row = blockIdx.x * blockDim.x + threadIdx.x;
    if (row < SCAN_NB) g_scan_desc[row] = 0ull;
    if (row >= NN) return;
    g_deg[row] = 0;
    float xv[DIM];
    const float4* xin = reinterpret_cast<const float4*>(in + row * DIM);
    #pragma unroll
    for (int q = 0; q < 8; q++) {
        float4 v = xin[q];
        xv[q * 4 + 0] = v.x; xv[q * 4 + 1] = v.y;
        xv[q * 4 + 2] = v.z; xv[q * 4 + 3] = v.w;
    }
    float4* o = reinterpret_cast<float4*>(g_a + row * DIM);
    #pragma unroll
    for (int jq = 0; jq < 8; jq++) {
        float4 r;
        #pragma unroll
        for (int jj = 0; jj < 4; jj++) {
            int j = jq * 4 + jj;
            float acc = 0.f;
            #pragma unroll
            for (int k = 0; k < DIM; k++) acc = fmaf(xv[k], sW[j * DIM + k], acc);
            (&r.x)[jj] = acc;
        }
        o[jq] = r;
    }
}

// ---------------- launch 1: degree count ----------------
__global__ void k_count(const int* __restrict__ dst) {
    int i = blockIdx.x * blockDim.x + threadIdx.x;
    if (i < NE) atomicAdd(&g_deg[dst[i]], 1);
}

// ---------------- launch 2: single-pass scan (decoupled lookback) + dis + cursor ----------------
__global__ void __launch_bounds__(SCAN_B) k_scan() {
    __shared__ int s[SCAN_B];
    __shared__ int s_tot;
    __shared__ int s_excl;
    int t = threadIdx.x, b = blockIdx.x;
    int idx = b * SCAN_B + t;
    int v = (idx < NN) ? g_deg[idx] : 0;
    if (idx < NN) g_dis[idx] = rsqrtf((float)(v + 1));   // +1 self-loop
    s[t] = v;
    __syncthreads();
    #pragma unroll
    for (int off = 1; off < SCAN_B; off <<= 1) {
        int tv = (t >= off) ? s[t - off] : 0;
        __syncthreads();
        s[t] += tv;
        __syncthreads();
    }
    int incl = s[t];
    if (t == SCAN_B - 1) {
        s_tot = incl;
        unsigned long long flag = (b == 0) ? 2ull : 1ull;
        atomicExch(&g_scan_desc[b], ((unsigned long long)(unsigned)incl << 32) | flag);
    }
    __syncthreads();
    if (t < 32) {
        int excl = 0;
        if (b > 0) {
            int j = b - 1;
            for (;;) {
                int jj = j - t;                      // lane t inspects block jj
                unsigned long long d = 0;
                if (jj >= 0) {
                    do { d = ((volatile unsigned long long*)g_scan_desc)[jj]; }
                    while ((d & 3ull) == 0);
                }
                unsigned fl = (unsigned)(d & 3ull);
                int val = (int)(unsigned)(d >> 32);
                unsigned pmask = __ballot_sync(0xffffffffu, (jj >= 0) && fl == 2u);
                if (pmask) {
                    int L = __ffs(pmask) - 1;        // closest predecessor with full prefix
                    int contrib = (t <= L) ? val : 0;
                    #pragma unroll
                    for (int o = 16; o > 0; o >>= 1) contrib += __shfl_down_sync(~0u, contrib, o);
                    excl += __shfl_sync(~0u, contrib, 0);
                    break;
                } else {
                    int contrib = (jj >= 0) ? val : 0;
                    #pragma unroll
                    for (int o = 16; o > 0; o >>= 1) contrib += __shfl_down_sync(~0u, contrib, o);
                    excl += __shfl_sync(~0u, contrib, 0);
                    j -= 32;
                }
            }
        }
        if (t == 0) {
            s_excl = excl;
            if (b > 0)
                atomicExch(&g_scan_desc[b],
                           ((unsigned long long)(unsigned)(excl + s_tot) << 32) | 2ull);
        }
    }
    __syncthreads();
    if (idx < NN) {
        int r = s_excl + incl - v;                   // exclusive prefix
        g_rowptr[idx] = r;
        g_cursor[idx] = r;
    }
    if (b == 0 && t == 0) g_rowptr[NN] = NE;
}

// ---------------- launch 3: CSR fill with precomputed dis[src] payload ----------------
__global__ void k_fill(const int* __restrict__ src, const int* __restrict__ dst) {
    int i = blockIdx.x * blockDim.x + threadIdx.x;
    if (i >= NE) return;
    int d = dst[i];
    int s = src[i];
    int pos = atomicAdd(&g_cursor[d], 1);
    g_edge[pos] = make_int2(s, __float_as_int(g_dis[s]));
}

// ---------------- launches 4,5: GCN gather, persistent warps ----------------
// v = relu( dis[d] * sum_{s in nbr(d)} dis[s]*xw[s] + dis[d]^2 * xw[d] + bias )
// PHASE 0: g_a -> g_b, fused with layer-2 linear W2.  PHASE 1: g_b -> g_h.
#define GATHER_GRID 1184
template <int PHASE>
__global__ void __launch_bounds__(256) k_gather(const float* __restrict__ bias,
                                                const float* __restrict__ W2) {
    const float* __restrict__ xw = (PHASE == 0) ? g_a : g_b;
    float* __restrict__ out      = (PHASE == 0) ? g_b : g_h;
    __shared__ float sW[DIM * 33];
    if (PHASE == 0) {
        for (int i = threadIdx.x; i < DIM * DIM; i += blockDim.x)
            sW[(i >> 5) * 33 + (i & 31)] = W2[i];
        __syncthreads();
    }
    int lane = threadIdx.x & 31;
    float bias_l = bias[lane];
    int warp = (blockIdx.x * blockDim.x + threadIdx.x) >> 5;
    int nwarps = (gridDim.x * blockDim.x) >> 5;
    for (int d = warp; d < NN; d += nwarps) {
        int start = g_rowptr[d];
        int end = g_rowptr[d + 1];
        float acc = 0.f;
        for (int base = start; base < end; base += 32) {
            int idx = base + lane;
            int2 e = (idx < end) ? g_edge[idx] : make_int2(0, 0);
            int m = min(32, end - base);
            int k = 0;
            for (; k + 1 < m; k += 2) {
                int s0 = __shfl_sync(~0u, e.x, k);
                float w0 = __int_as_float(__shfl_sync(~0u, e.y, k));
                int s1 = __shfl_sync(~0u, e.x, k + 1);
                float w1 = __int_as_float(__shfl_sync(~0u, e.y, k + 1));
                float v0 = xw[s0 * DIM + lane];
                float v1 = xw[s1 * DIM + lane];
                acc = fmaf(v0, w0, acc);
                acc = fmaf(v1, w1, acc);
            }
            if (k < m) {
                int s0 = __shfl_sync(~0u, e.x, k);
                float w0 = __int_as_float(__shfl_sync(~0u, e.y, k));
                acc = fmaf(xw[s0 * DIM + lane], w0, acc);
            }
        }
        float dd = g_dis[d];
        float v = fmaxf(fmaf(dd, acc, fmaf(dd * dd, xw[d * DIM + lane], bias_l)), 0.f);
        if (PHASE == 1) {
            out[d * DIM + lane] = v;
        } else {
            float o = 0.f;
            #pragma unroll
            for (int k2 = 0; k2 < DIM; k2++)
                o = fmaf(__shfl_sync(~0u, v, k2), sW[lane * 33 + k2], o);
            out[d * DIM + lane] = o;
        }
    }
}

// ---------------- launch 6: triple embedding + dueling MLP heads, persistent warps ----------------
__device__ __forceinline__ float lay(float x, const float* sw, const float* sb, int lane) {
    float acc = sb[lane];
    #pragma unroll
    for (int k = 0; k < DIM; k++)
        acc = fmaf(__shfl_sync(0xffffffffu, x, k), sw[lane * 33 + k], acc);
    return fmaxf(acc, 0.f);
}

#define TRIPLE_GRID 592
__global__ void __launch_bounds__(256) k_triple(
    const int* __restrict__ head, const int* __restrict__ tail, const int* __restrict__ rel,
    const float* __restrict__ rel_emb,
    const float* __restrict__ aw1, const float* __restrict__ ab1,
    const float* __restrict__ aw2, const float* __restrict__ ab2,
    const float* __restrict__ aw3, const float* __restrict__ ab3,
    const float* __restrict__ vw1, const float* __restrict__ vb1,
    const float* __restrict__ vw2, const float* __restrict__ vb2,
    const float* __restrict__ vw3, const float* __restrict__ vb3,
    float* __restrict__ out) {
    __shared__ float s_aw1[DIM * 33], s_aw2[DIM * 33], s_vw1[DIM * 33], s_vw2[DIM * 33];
    __shared__ float s_aw3[3 * 33], s_vw3[DIM];
    __shared__ float s_ab1[DIM], s_ab2[DIM], s_ab3[3], s_vb1[DIM], s_vb2[DIM];
    __shared__ float s_vb3;
    __shared__ float s_rel[NR * DIM];
    int tid = threadIdx.x;
    for (int i = tid; i < DIM * DIM; i += blockDim.x) {
        int r = i >> 5, c = i & 31;
        s_aw1[r * 33 + c] = aw1[i];
        s_aw2[r * 33 + c] = aw2[i];
        s_vw1[r * 33 + c] = vw1[i];
        s_vw2[r * 33 + c] = vw2[i];
    }
    for (int i = tid; i < 3 * DIM; i += blockDim.x) s_aw3[(i >> 5) * 33 + (i & 31)] = aw3[i];
    for (int i = tid; i < NR * DIM; i += blockDim.x) s_rel[i] = rel_emb[i];
    if (tid < DIM) {
        s_vw3[tid] = vw3[tid];
        s_ab1[tid] = ab1[tid]; s_ab2[tid] = ab2[tid];
        s_vb1[tid] = vb1[tid]; s_vb2[tid] = vb2[tid];
    }
    if (tid < 3) s_ab3[tid] = ab3[tid];
    if (tid == 0) s_vb3 = vb3[0];
    __syncthreads();

    int lane = tid & 31;
    int warp = (blockIdx.x * blockDim.x + tid) >> 5;
    int nwarps = (gridDim.x * blockDim.x) >> 5;
    for (int w = warp; w < NT; w += nwarps) {
        int hd = head[w], tl = tail[w], r = rel[w];
        float xv = g_h[hd * DIM + lane] + s_rel[r * DIM + lane] + g_h[tl * DIM + lane];

        float a = lay(xv, s_aw1, s_ab1, lane);
        a = lay(a, s_aw2, s_ab2, lane);
        float v = lay(xv, s_vw1, s_vb1, lane);
        v = lay(v, s_vw2, s_vb2, lane);

        float a3 = (lane < 3) ? s_ab3[lane] : 0.f;
        float vacc = 0.f;
        #pragma unroll
        for (int k = 0; k < DIM; k++) {
            float ha = __shfl_sync(0xffffffffu, a, k);
            float hv = __shfl_sync(0xffffffffu, v, k);
            if (lane < 3) a3 = fmaf(ha, s_aw3[lane * 33 + k], a3);
            vacc = fmaf(hv, s_vw3[k], vacc);
        }
        float val = s_vb3 + vacc;
        float a0 = __shfl_sync(0xffffffffu, a3, 0);
        float a1 = __shfl_sync(0xffffffffu, a3, 1);
        float a2 = __shfl_sync(0xffffffffu, a3, 2);
        float mean = (a0 + a1 + a2) * (1.f / 3.f);
        if (lane < 3) out[w * 3 + lane] = val + a3 - mean;
    }
}

// ---------------- launch: pure kernel launches, only real device pointers ----------------
extern "C" void kernel_launch(void* const* d_in, const int* in_sizes, int n_in,
                              void* d_out, int out_size) {
    (void)in_sizes; (void)n_in; (void)out_size;
    const float* x       = (const float*)d_in[0];
    const int*   ei      = (const int*)d_in[1];
    const int*   head    = (const int*)d_in[2];
    const int*   tail    = (const int*)d_in[3];
    const int*   rel     = (const int*)d_in[4];
    const float* rel_emb = (const float*)d_in[5];
    const float* gw1 = (const float*)d_in[6];
    const float* gb1 = (const float*)d_in[7];
    const float* gw2 = (const float*)d_in[8];
    const float* gb2 = (const float*)d_in[9];
    const float* aw1 = (const float*)d_in[10];
    const float* ab1 = (const float*)d_in[11];
    const float* aw2 = (const float*)d_in[12];
    const float* ab2 = (const float*)d_in[13];
    const float* aw3 = (const float*)d_in[14];
    const float* ab3 = (const float*)d_in[15];
    const float* vw1 = (const float*)d_in[16];
    const float* vb1 = (const float*)d_in[17];
    const float* vw2 = (const float*)d_in[18];
    const float* vb2 = (const float*)d_in[19];
    const float* vw3 = (const float*)d_in[20];
    const float* vb3 = (const float*)d_in[21];
    float* out = (float*)d_out;

    const int* src = ei;
    const int* dst = ei + NE;

    k_mm_init<<<(NN + 255) / 256, 256>>>(x, gw1);        // 0: g_a = x@W1^T, zero deg/flags
    k_count<<<(NE + 255) / 256, 256>>>(dst);             // 1: degrees
    k_scan<<<SCAN_NB, SCAN_B>>>();                       // 2: rowptr/cursor/dis (single pass)
    k_fill<<<(NE + 255) / 256, 256>>>(src, dst);         // 3: CSR fill
    k_gather<0><<<GATHER_GRID, 256>>>(gb1, gw2);         // 4: L1 aggregate+relu+W2
    k_gather<1><<<GATHER_GRID, 256>>>(gb2, nullptr);     // 5: L2 aggregate+relu (ncu slot)
    k_triple<<<TRIPLE_GRID, 256>>>(head, tail, rel, rel_emb,
                                   aw1, ab1, aw2, ab2, aw3, ab3,
                                   vw1, vb1, vw2, vb2, vw3, vb3, out);  // 6
}